// round 1
// baseline (speedup 1.0000x reference)
#include <cuda_runtime.h>

// Fuzzyfier: out[b,v,s,p] = mv if mv >= 0.1 else 0
//   mv = exp( -(x[b,v,s]-c[v,p])^2 / (2*sigma[v,p]^2) )
// Shapes: x (64,8,1024) f32, fuzzy_sets (8,64,2) f32, out (64,8,1024,64) f32.
// Pure HBM-write-bound: 128 MiB output, ~2 MiB input.

#define SEQ   1024
#define NP    64
#define NV    8
#define ALPHA 0.1f

__global__ __launch_bounds__(256, 8)
void fuzzyfier_kernel(const float* __restrict__ x,
                      const float* __restrict__ fs,
                      float4* __restrict__ out)
{
    __shared__ float s_c[NP];   // centers for this v
    __shared__ float s_k[NP];   // 1/(2*sigma^2) for this v

    const int tid = threadIdx.x;
    const int bv  = blockIdx.y;          // b*NV + v
    const int v   = bv & (NV - 1);

    if (tid < NP) {
        float c  = fs[(v * NP + tid) * 2 + 0];
        float sg = fs[(v * NP + tid) * 2 + 1];
        s_c[tid] = c;
        s_k[tid] = 1.0f / (2.0f * sg * sg);
    }
    __syncthreads();

    const int p4 = tid & 15;    // which float4 within the 64-wide P row
    const int sl = tid >> 4;    // 0..15: s-lane within the block tile

    const float4 c = reinterpret_cast<const float4*>(s_c)[p4];
    const float4 k = reinterpret_cast<const float4*>(s_k)[p4];

    const int s_base = blockIdx.x * 64;

    #pragma unroll
    for (int i = 0; i < 4; i++) {
        const int s  = s_base + i * 16 + sl;
        const float xv = x[bv * SEQ + s];

        float d;
        float4 r;
        d = xv - c.x; r.x = expf(-(d * d) * k.x);
        d = xv - c.y; r.y = expf(-(d * d) * k.y);
        d = xv - c.z; r.z = expf(-(d * d) * k.z);
        d = xv - c.w; r.w = expf(-(d * d) * k.w);

        r.x = (r.x >= ALPHA) ? r.x : 0.0f;
        r.y = (r.y >= ALPHA) ? r.y : 0.0f;
        r.z = (r.z >= ALPHA) ? r.z : 0.0f;
        r.w = (r.w >= ALPHA) ? r.w : 0.0f;

        out[(size_t)(bv * SEQ + s) * 16 + p4] = r;
    }
}

extern "C" void kernel_launch(void* const* d_in, const int* in_sizes, int n_in,
                              void* d_out, int out_size)
{
    const float* x  = (const float*)d_in[0];          // (64,8,1024)
    const float* fs = (const float*)d_in[1];          // (8,64,2)
    float4* out     = (float4*)d_out;                 // (64,8,1024,64)

    // B*V derived from input size so shape changes don't silently break.
    const int BV = in_sizes[0] / SEQ;                 // 512

    dim3 grid(SEQ / 64, BV);
    fuzzyfier_kernel<<<grid, 256>>>(x, fs, out);
}

// round 2
// speedup vs baseline: 1.2355x; 1.2355x over previous
#include <cuda_runtime.h>

// Fuzzyfier: out[b,v,s,p] = mv if mv >= 0.1 else 0
//   mv = exp(-(x-c)^2 / (2 sigma^2)) = exp2((x-c)^2 * negk),
//   negk = -log2(e) / (2 sigma^2)   (precomputed per (v,p) in shared)
// Shapes: x (64,8,1024) f32, fuzzy_sets (8,64,2) f32, out (64,8,1024,64) f32.
// 134 MB write-once output -> HBM-write-bound once exp is reduced to 1 MUFU.

#define SEQ   1024
#define NP    64
#define NV    8
#define ALPHA 0.1f

__device__ __forceinline__ float ex2_approx(float a) {
    float r;
    asm("ex2.approx.f32 %0, %1;" : "=f"(r) : "f"(a));
    return r;
}

__global__ __launch_bounds__(256, 8)
void fuzzyfier_kernel(const float* __restrict__ x,
                      const float* __restrict__ fs,
                      float4* __restrict__ out)
{
    __shared__ float s_c[NP];   // centers for this v
    __shared__ float s_k[NP];   // -log2(e)/(2*sigma^2) for this v

    const int tid = threadIdx.x;
    const int bv  = blockIdx.y;          // b*NV + v
    const int v   = bv & (NV - 1);

    if (tid < NP) {
        float c  = fs[(v * NP + tid) * 2 + 0];
        float sg = fs[(v * NP + tid) * 2 + 1];
        s_c[tid] = c;
        // -log2(e) / (2 sigma^2)
        s_k[tid] = -1.4426950408889634f / (2.0f * sg * sg);
    }
    __syncthreads();

    const int p4 = tid & 15;    // which float4 within the 64-wide P row
    const int sl = tid >> 4;    // 0..15: s-lane within the block tile

    const float4 c = reinterpret_cast<const float4*>(s_c)[p4];
    const float4 k = reinterpret_cast<const float4*>(s_k)[p4];

    const int s_base = blockIdx.x * 64;

    #pragma unroll
    for (int i = 0; i < 4; i++) {
        const int s  = s_base + i * 16 + sl;
        const float xv = __ldg(&x[bv * SEQ + s]);

        float d;
        float4 r;
        d = xv - c.x; r.x = ex2_approx(d * d * k.x);
        d = xv - c.y; r.y = ex2_approx(d * d * k.y);
        d = xv - c.z; r.z = ex2_approx(d * d * k.z);
        d = xv - c.w; r.w = ex2_approx(d * d * k.w);

        r.x = (r.x >= ALPHA) ? r.x : 0.0f;
        r.y = (r.y >= ALPHA) ? r.y : 0.0f;
        r.z = (r.z >= ALPHA) ? r.z : 0.0f;
        r.w = (r.w >= ALPHA) ? r.w : 0.0f;

        // streaming store: write-once output, don't pollute L2
        __stcs(&out[(size_t)(bv * SEQ + s) * 16 + p4], r);
    }
}

extern "C" void kernel_launch(void* const* d_in, const int* in_sizes, int n_in,
                              void* d_out, int out_size)
{
    const float* x  = (const float*)d_in[0];          // (64,8,1024)
    const float* fs = (const float*)d_in[1];          // (8,64,2)
    float4* out     = (float4*)d_out;                 // (64,8,1024,64)

    const int BV = in_sizes[0] / SEQ;                 // 512

    dim3 grid(SEQ / 64, BV);
    fuzzyfier_kernel<<<grid, 256>>>(x, fs, out);
}

// round 3
// speedup vs baseline: 1.2516x; 1.0130x over previous
#include <cuda_runtime.h>

// Fuzzyfier: out[b,v,s,p] = mv if mv >= 0.1 else 0
//   mv = exp(-(x-c)^2 / (2 sigma^2)) = exp2((x-c)^2 * negk),
//   negk = -log2(e)/(2 sigma^2)  (precomputed per (v,p) in shared)
// Shapes: x (64,8,1024) f32, fuzzy_sets (8,64,2) f32, out (64,8,1024,64) f32.
// 134 MB write-once output. Round 3: MLP restructure — prefetch x, batch
// compute->4x independent STG.128, bigger per-thread tile.

#define SEQ   1024
#define NP    64
#define NV    8
#define ALPHA 0.1f
#define S_PER_BLOCK 128   // s-rows per block
#define ITERS 8           // float4 stores per thread

__device__ __forceinline__ float ex2_approx(float a) {
    float r;
    asm("ex2.approx.f32 %0, %1;" : "=f"(r) : "f"(a));
    return r;
}

__device__ __forceinline__ float4 fuzz4(float xv, float4 c, float4 k) {
    float d;
    float4 r;
    d = xv - c.x; r.x = ex2_approx(d * d * k.x);
    d = xv - c.y; r.y = ex2_approx(d * d * k.y);
    d = xv - c.z; r.z = ex2_approx(d * d * k.z);
    d = xv - c.w; r.w = ex2_approx(d * d * k.w);
    r.x = (r.x >= ALPHA) ? r.x : 0.0f;
    r.y = (r.y >= ALPHA) ? r.y : 0.0f;
    r.z = (r.z >= ALPHA) ? r.z : 0.0f;
    r.w = (r.w >= ALPHA) ? r.w : 0.0f;
    return r;
}

__global__ __launch_bounds__(256, 4)
void fuzzyfier_kernel(const float* __restrict__ x,
                      const float* __restrict__ fs,
                      float4* __restrict__ out)
{
    __shared__ float s_c[NP];   // centers for this v
    __shared__ float s_k[NP];   // -log2(e)/(2*sigma^2) for this v

    const int tid = threadIdx.x;
    const int bv  = blockIdx.y;          // b*NV + v
    const int v   = bv & (NV - 1);

    if (tid < NP) {
        float c  = fs[(v * NP + tid) * 2 + 0];
        float sg = fs[(v * NP + tid) * 2 + 1];
        s_c[tid] = c;
        s_k[tid] = -1.4426950408889634f / (2.0f * sg * sg);
    }
    __syncthreads();

    const int p4 = tid & 15;    // float4 index within 64-wide P row
    const int sl = tid >> 4;    // 0..15: s-lane

    const float4 c = reinterpret_cast<const float4*>(s_c)[p4];
    const float4 k = reinterpret_cast<const float4*>(s_k)[p4];

    const int s0 = blockIdx.x * S_PER_BLOCK + sl;   // first s this thread owns
    const float* xp = x + bv * SEQ + s0;

    // Prefetch all 8 x values (independent broadcast LDGs in flight).
    float xv[ITERS];
    #pragma unroll
    for (int i = 0; i < ITERS; i++)
        xv[i] = __ldg(&xp[i * 16]);

    // Base store pointer; iteration stride = 16 s-rows * 16 float4 = 256 float4.
    float4* op = out + (size_t)(bv * SEQ + s0) * 16 + p4;

    // Batch 1: compute 4 results, then 4 independent streaming stores.
    float4 r0 = fuzz4(xv[0], c, k);
    float4 r1 = fuzz4(xv[1], c, k);
    float4 r2 = fuzz4(xv[2], c, k);
    float4 r3 = fuzz4(xv[3], c, k);
    __stcs(op + 0 * 256, r0);
    __stcs(op + 1 * 256, r1);
    __stcs(op + 2 * 256, r2);
    __stcs(op + 3 * 256, r3);

    // Batch 2.
    float4 r4 = fuzz4(xv[4], c, k);
    float4 r5 = fuzz4(xv[5], c, k);
    float4 r6 = fuzz4(xv[6], c, k);
    float4 r7 = fuzz4(xv[7], c, k);
    __stcs(op + 4 * 256, r4);
    __stcs(op + 5 * 256, r5);
    __stcs(op + 6 * 256, r6);
    __stcs(op + 7 * 256, r7);
}

extern "C" void kernel_launch(void* const* d_in, const int* in_sizes, int n_in,
                              void* d_out, int out_size)
{
    const float* x  = (const float*)d_in[0];          // (64,8,1024)
    const float* fs = (const float*)d_in[1];          // (8,64,2)
    float4* out     = (float4*)d_out;                 // (64,8,1024,64)

    const int BV = in_sizes[0] / SEQ;                 // 512

    dim3 grid(SEQ / S_PER_BLOCK, BV);
    fuzzyfier_kernel<<<grid, 256>>>(x, fs, out);
}